// round 7
// baseline (speedup 1.0000x reference)
#include <cuda_runtime.h>
#include <cuda_fp16.h>
#include <cstdint>
#include <cstddef>

// ---------------- problem constants ----------------
// B=256, K=16, H=64, W=64, N=1024, F_IN=143 (=144 with zero-weight drop), HID=128, NCLS=16
// feature f = d*16 + k, d in 0..8 (3x3 neighborhood), drop = 64 + bs[n]

// ---------------- device scratch (static; no runtime alloc) ----------------
__device__ __align__(16) __half  g_zh[16u * 64u * 64u * 256u];   // z as fp16 (k,i,j,b), value = z/15
__device__ __align__(16) uint32_t g_w1p[16 * 9792];              // 16 W1-variant B-operand tables: [v][kp<72 stride136][h<128] half2(f=2kp, 2kp+1)
__device__ __align__(16) uint32_t g_w2p[1024];                   // W2 B-operand: [kp<64][c<16] half2
__device__ int g_counter;

// ---------------- helpers ----------------
__device__ __forceinline__ uint32_t pack_half2(float lo, float hi) {
    __half2 h = __floats2half2_rn(lo, hi);
    return *reinterpret_cast<uint32_t*>(&h);
}
__device__ __forceinline__ uint32_t pack_us(unsigned short lo, unsigned short hi) {
    return (uint32_t)lo | ((uint32_t)hi << 16);
}

__device__ __forceinline__ void mma16816(float& c0, float& c1, float& c2, float& c3,
                                         uint32_t a0, uint32_t a1, uint32_t a2, uint32_t a3,
                                         uint32_t b0, uint32_t b1) {
    asm volatile("mma.sync.aligned.m16n8k16.row.col.f32.f16.f16.f32 "
                 "{%0,%1,%2,%3}, {%4,%5,%6,%7}, {%8,%9}, {%0,%1,%2,%3};"
                 : "+f"(c0), "+f"(c1), "+f"(c2), "+f"(c3)
                 : "r"(a0), "r"(a1), "r"(a2), "r"(a3), "r"(b0), "r"(b1));
}

// ---------------- prep: z (B,K,H,W) int32 -> g_zh (K,H,W,B) fp16 of z/15 ----------------
// grid 1024 = (k,i), 256 threads. Reads coalesced over j, writes coalesced over b.
__global__ void __launch_bounds__(256) prep_zh(const int* __restrict__ z) {
    __shared__ __half tile[64][264];       // [j][b], padded
    const int k = blockIdx.x >> 6, i = blockIdx.x & 63;
    const int t = threadIdx.x;
    const int j = t & 63, b0 = t >> 6;     // b0 in 0..3

    const int* src = z + k * 4096 + i * 64 + j;
#pragma unroll 8
    for (int it = 0; it < 64; it++) {
        int b = b0 * 64 + it;
        tile[j][b] = __float2half((float)src[(size_t)b << 16] * (1.0f / 15.0f));
    }
    __syncthreads();

    __half* dst = g_zh + ((size_t)k << 20) + ((size_t)i << 14);
#pragma unroll
    for (int it = 0; it < 8; it++) {
        int w = t + (it << 8);             // 0..2047 uint4-units
        int jo = w >> 5, q = w & 31;
        uint4 v = *reinterpret_cast<const uint4*>(&tile[jo][q * 8]);
        *reinterpret_cast<uint4*>(dst + jo * 256 + q * 8) = v;
    }
}

// ---------------- prep: W1 variants + W2 packs (+ zero counter) ----------------
// grid (73, 16), 128 threads. blockIdx.x<72: W1 variant pack. blockIdx.x==72 && y==0: W2 pack.
__global__ void __launch_bounds__(128) prep_w(const float* __restrict__ W1,
                                              const float* __restrict__ W2) {
    const int h = threadIdx.x;             // 0..127
    if (blockIdx.x < 72) {
        const int kp = blockIdx.x;         // 0..71  (feature pair f=2kp, 2kp+1)
        const int v  = blockIdx.y;         // 0..15
        const int drop = 64 + v;
        const int f0 = 2 * kp, f1 = 2 * kp + 1;
        float x0 = (f0 == drop) ? 0.f : W1[(f0 - (f0 > drop)) * 128 + h];
        float x1 = (f1 == drop) ? 0.f : W1[(f1 - (f1 > drop)) * 128 + h];
        g_w1p[v * 9792 + kp * 136 + h] = pack_half2(x0, x1);
    } else if (blockIdx.y == 0) {
        if (h == 0) g_counter = 0;
#pragma unroll
        for (int e = 0; e < 8; e++) {
            int idx = h + 128 * e;         // = kp*16 + c
            int kp = idx >> 4, c = idx & 15;
            g_w2p[idx] = pack_half2(W2[(2 * kp) * 16 + c], W2[(2 * kp + 1) * 16 + c]);
        }
    }
}

__global__ void finalize_kernel(float* out) {
    out[0] = (float)g_counter * (1.0f / 262144.0f);   // N*B = 2^18
}

// ---------------- main kernel ----------------
// grid (1024, 2): n = blockIdx.x, b-half = blockIdx.y. 256 threads = 8 warps, M=16 rows each.
__global__ void __launch_bounds__(256, 2)
main_kernel(const int* __restrict__ z, const int* __restrict__ bs,
            const int* __restrict__ ii, const int* __restrict__ jj,
            const float* __restrict__ b1, const float* __restrict__ b2)
{
    __shared__ __align__(16) uint32_t w1s[9792];   // [kp stride 136][h] half2 — conflict-free for B-frag reads
    __shared__ __align__(16) uint32_t w2s[1024];   // [kp][c]
    __shared__ float b1s[128];
    __shared__ float b2s[16];

    const int tid  = threadIdx.x;
    const int lane = tid & 31;
    const int wm   = tid >> 5;             // warp id = M-tile
    const int tig  = lane & 3;             // thread-in-group
    const int gid  = lane >> 2;            // group id
    const int n = blockIdx.x, mhalf = blockIdx.y;

    const int bsv = __ldg(bs + n), iiv = __ldg(ii + n), jjv = __ldg(jj + n);

    // ---- stage weights/biases ----
    {
        const uint4* s1 = reinterpret_cast<const uint4*>(g_w1p + (size_t)bsv * 9792);
        uint4* d1 = reinterpret_cast<uint4*>(w1s);
        for (int i = tid; i < 2448; i += 256) d1[i] = s1[i];
        reinterpret_cast<uint4*>(w2s)[tid] = reinterpret_cast<const uint4*>(g_w2p)[tid];
        if (tid < 128) b1s[tid] = b1[tid];
        if (tid < 16)  b2s[tid] = b2[tid];
    }
    __syncthreads();

    // ---- MMA1: c[16 n-tiles][4] = ctx(128b x 144f) @ W1eff(144 x 128h), per-warp M=16 ----
    float c[16][4];
#pragma unroll
    for (int t = 0; t < 16; t++) { c[t][0] = 0.f; c[t][1] = 0.f; c[t][2] = 0.f; c[t][3] = 0.f; }

    const int b_lo = mhalf * 128 + wm * 16 + gid;   // absolute b for row gid
    const int k0 = 2 * tig;
    const unsigned short* zh = reinterpret_cast<const unsigned short*>(g_zh);

#pragma unroll
    for (int s = 0; s < 9; s++) {
        const int ni = (iiv + (s / 3) + 63) & 63;
        const int nj = (jjv + (s % 3) + 63) & 63;
        const unsigned short* p = zh + (((size_t)ni << 14) + ((size_t)nj << 8));
        // A fragment: rows {gid, gid+8} (b), cols {k0, k0+1, k0+8, k0+9} (k channel, d=s)
        uint32_t a0 = pack_us(p[((size_t)(k0)     << 20) + b_lo],     p[((size_t)(k0 + 1) << 20) + b_lo]);
        uint32_t a1 = pack_us(p[((size_t)(k0)     << 20) + b_lo + 8], p[((size_t)(k0 + 1) << 20) + b_lo + 8]);
        uint32_t a2 = pack_us(p[((size_t)(k0 + 8) << 20) + b_lo],     p[((size_t)(k0 + 9) << 20) + b_lo]);
        uint32_t a3 = pack_us(p[((size_t)(k0 + 8) << 20) + b_lo + 8], p[((size_t)(k0 + 9) << 20) + b_lo + 8]);

        const uint32_t* w0 = w1s + (8 * s + tig) * 136 + gid;
        const uint32_t* w4 = w0 + 4 * 136;
#pragma unroll
        for (int t = 0; t < 16; t++) {
            uint32_t bb0 = w0[8 * t];
            uint32_t bb1 = w4[8 * t];
            mma16816(c[t][0], c[t][1], c[t][2], c[t][3], a0, a1, a2, a3, bb0, bb1);
        }
    }

    // ---- layer 2: h = relu(c + b1) chained as A-fragments; d2 = h @ W2 ----
    float d20[4] = {0.f, 0.f, 0.f, 0.f};
    float d21[4] = {0.f, 0.f, 0.f, 0.f};
#pragma unroll
    for (int s = 0; s < 8; s++) {
        float2 bbl = reinterpret_cast<const float2*>(b1s)[8 * s + tig];
        float2 bbh = reinterpret_cast<const float2*>(b1s)[8 * s + tig + 4];
        // A-frag cols = h indices {16s+2tig, +1, +8, +9} -> accum tiles 2s (cols+0) and 2s+1 (cols+8)
        uint32_t a0 = pack_half2(fmaxf(c[2 * s][0] + bbl.x, 0.f),     fmaxf(c[2 * s][1] + bbl.y, 0.f));
        uint32_t a1 = pack_half2(fmaxf(c[2 * s][2] + bbl.x, 0.f),     fmaxf(c[2 * s][3] + bbl.y, 0.f));
        uint32_t a2 = pack_half2(fmaxf(c[2 * s + 1][0] + bbh.x, 0.f), fmaxf(c[2 * s + 1][1] + bbh.y, 0.f));
        uint32_t a3 = pack_half2(fmaxf(c[2 * s + 1][2] + bbh.x, 0.f), fmaxf(c[2 * s + 1][3] + bbh.y, 0.f));

        uint32_t b00 = w2s[(8 * s + tig) * 16 + gid];
        uint32_t b01 = w2s[(8 * s + tig + 4) * 16 + gid];
        mma16816(d20[0], d20[1], d20[2], d20[3], a0, a1, a2, a3, b00, b01);
        uint32_t b10 = w2s[(8 * s + tig) * 16 + 8 + gid];
        uint32_t b11 = w2s[(8 * s + tig + 4) * 16 + 8 + gid];
        mma16816(d21[0], d21[1], d21[2], d21[3], a0, a1, a2, a3, b10, b11);
    }

    // ---- epilogue: argmax(logits + b2) per row, compare to target, count ----
    float2 q0 = reinterpret_cast<const float2*>(b2s)[tig];       // classes 2tig, 2tig+1
    float2 q1 = reinterpret_cast<const float2*>(b2s)[tig + 4];   // classes 8+2tig, 9+2tig

    // row lo (b = b_lo): candidates in ascending class order
    float vl0 = d20[0] + q0.x, vl1 = d20[1] + q0.y, vl2 = d21[0] + q1.x, vl3 = d21[1] + q1.y;
    float bestl = vl0; int bil = 2 * tig;
    if (vl1 > bestl) { bestl = vl1; bil = 2 * tig + 1; }
    if (vl2 > bestl) { bestl = vl2; bil = 8 + 2 * tig; }
    if (vl3 > bestl) { bestl = vl3; bil = 9 + 2 * tig; }
    // row hi (b = b_lo + 8)
    float vh0 = d20[2] + q0.x, vh1 = d20[3] + q0.y, vh2 = d21[2] + q1.x, vh3 = d21[3] + q1.y;
    float besth = vh0; int bih = 2 * tig;
    if (vh1 > besth) { besth = vh1; bih = 2 * tig + 1; }
    if (vh2 > besth) { besth = vh2; bih = 8 + 2 * tig; }
    if (vh3 > besth) { besth = vh3; bih = 9 + 2 * tig; }

#pragma unroll
    for (int off = 1; off <= 2; off <<= 1) {
        float ov = __shfl_xor_sync(0xffffffffu, bestl, off);
        int   oi = __shfl_xor_sync(0xffffffffu, bil, off);
        if (ov > bestl || (ov == bestl && oi < bil)) { bestl = ov; bil = oi; }
        ov = __shfl_xor_sync(0xffffffffu, besth, off);
        oi = __shfl_xor_sync(0xffffffffu, bih, off);
        if (ov > besth || (ov == besth && oi < bih)) { besth = ov; bih = oi; }
    }

    unsigned errs = 0;
    if (tig == 0) {
        const size_t toff = (size_t)bsv * 4096 + (size_t)iiv * 64 + jjv;
        int tlo = __ldg(z + ((size_t)b_lo << 16) + toff);
        int thi = __ldg(z + ((size_t)(b_lo + 8) << 16) + toff);
        errs = (unsigned)(bil != tlo) + (unsigned)(bih != thi);
    }
    unsigned tot = __reduce_add_sync(0xffffffffu, errs);
    if (lane == 0) atomicAdd(&g_counter, (int)tot);
}

// ---------------- launch ----------------
extern "C" void kernel_launch(void* const* d_in, const int* in_sizes, int n_in,
                              void* d_out, int out_size) {
    (void)in_sizes; (void)n_in; (void)out_size;
    const int*   z  = (const int*)d_in[0];
    const int*   bs = (const int*)d_in[1];
    const int*   ii = (const int*)d_in[2];
    const int*   jj = (const int*)d_in[3];
    const float* W1 = (const float*)d_in[4];
    const float* b1 = (const float*)d_in[5];
    const float* W2 = (const float*)d_in[6];
    const float* b2 = (const float*)d_in[7];

    prep_zh<<<1024, 256>>>(z);
    prep_w<<<dim3(73, 16), 128>>>(W1, W2);
    main_kernel<<<dim3(1024, 2), 256>>>(z, bs, ii, jj, b1, b2);
    finalize_kernel<<<1, 1>>>((float*)d_out);
}